// round 9
// baseline (speedup 1.0000x reference)
#include <cuda_runtime.h>
#include <cuda_bf16.h>
#include <stdint.h>

#define B_ROWS   4096
#define D_MODEL  768
#define DICT     24576
#define K_TOP    64
#define CAND_CAP 512
#define MARGIN   0.1f

// ---------------- scratch (device globals) ----------------
__device__ __nv_bfloat16 g_xb[(size_t)B_ROWS * D_MODEL];    // x in bf16
__device__ __nv_bfloat16 g_wb[(size_t)DICT * D_MODEL];      // W_enc in bf16
__device__ __nv_bfloat16 g_preh[(size_t)B_ROWS * DICT];     // screened pre_acts (bf16)
__device__ float g_wdt[(size_t)DICT * D_MODEL];             // W_dec transposed
__device__ int   g_idx[(size_t)B_ROWS * K_TOP];
__device__ float g_val[(size_t)B_ROWS * K_TOP];

__device__ __forceinline__ uint32_t smem_u32(const void* p) {
    uint32_t a;
    asm("{ .reg .u64 t; cvta.to.shared.u64 t, %1; cvt.u32.u64 %0, t; }" : "=r"(a) : "l"(p));
    return a;
}

// ---------------- K0a: fp32 -> bf16 converts ----------------
__global__ void convert_bf16_kernel(const float* __restrict__ src,
                                    __nv_bfloat16* __restrict__ dst, int n4) {
    int i = blockIdx.x * blockDim.x + threadIdx.x;
    if (i < n4) {
        float4 v = ((const float4*)src)[i];
        __nv_bfloat162* o = (__nv_bfloat162*)dst;
        o[2 * i]     = __floats2bfloat162_rn(v.x, v.y);
        o[2 * i + 1] = __floats2bfloat162_rn(v.z, v.w);
    }
}

// ---------------- K0b: transpose W_dec [D][F] -> g_wdt [F][D] ----------------
__global__ void transpose_wdec_kernel(const float* __restrict__ wdec) {
    __shared__ float s[32][33];
    int f0 = blockIdx.x * 32;
    int d0 = blockIdx.y * 32;
    int tx = threadIdx.x, ty = threadIdx.y;
#pragma unroll
    for (int i = 0; i < 4; i++)
        s[ty + i * 8][tx] = wdec[(size_t)(d0 + ty + i * 8) * DICT + f0 + tx];
    __syncthreads();
#pragma unroll
    for (int i = 0; i < 4; i++)
        g_wdt[(size_t)(f0 + ty + i * 8) * D_MODEL + d0 + tx] = s[tx][ty + i * 8];
}

// ---------------- K1: bf16 mma.sync screening GEMM, 64x64 warp tiles ---------
#define PITCH 40
#define KCH   32
#define NCHUNKS (D_MODEL / KCH)   // 24
#define STAGE_BYTES (128 * PITCH * 2)
#define GEMM_SMEM   (6 * STAGE_BYTES)

__device__ __forceinline__ void cp16(uint32_t saddr, const void* g) {
    asm volatile("cp.async.ca.shared.global [%0], [%1], 16;" :: "r"(saddr), "l"(g));
}

__global__ __launch_bounds__(128, 2)
void gemm_enc_mma(const float* __restrict__ benc) {
    extern __shared__ __align__(128) char dsm[];
    __shared__ float s_bias[128];

    const int tid  = threadIdx.x;
    const int wid  = tid >> 5;
    const int lane = tid & 31;
    const int wm   = wid & 1;
    const int wn   = wid >> 1;
    const int m0 = blockIdx.y * 128;
    const int n0 = blockIdx.x * 128;

    if (tid < 128) s_bias[tid] = benc[n0 + tid];

    const __nv_bfloat16* Ag = g_xb + (size_t)m0 * D_MODEL;
    const __nv_bfloat16* Bg = g_wb + (size_t)n0 * D_MODEL;

    const uint32_t sA0 = smem_u32(dsm);
    const uint32_t sB0 = sA0 + 3 * STAGE_BYTES;

    auto issue = [&](int ch, int stg) {
#pragma unroll
        for (int i = 0; i < 4; i++) {
            int seg = tid + (i << 7);
            int r = seg >> 2, c = seg & 3;
            uint32_t so = (uint32_t)stg * STAGE_BYTES + (uint32_t)(r * PITCH + c * 8) * 2u;
            cp16(sA0 + so, Ag + (size_t)r * D_MODEL + ch * KCH + c * 8);
            cp16(sB0 + so, Bg + (size_t)r * D_MODEL + ch * KCH + c * 8);
        }
        asm volatile("cp.async.commit_group;" ::: "memory");
    };

    float c[4][8][4];
#pragma unroll
    for (int i = 0; i < 4; i++)
#pragma unroll
        for (int j = 0; j < 8; j++)
#pragma unroll
            for (int q = 0; q < 4; q++) c[i][j][q] = 0.f;

    issue(0, 0);
    issue(1, 1);

#pragma unroll 1
    for (int ch = 0; ch < NCHUNKS; ch++) {
        const int stg = ch % 3;
        if (ch + 1 < NCHUNKS)
            asm volatile("cp.async.wait_group 1;" ::: "memory");
        else
            asm volatile("cp.async.wait_group 0;" ::: "memory");
        __syncthreads();
        if (ch + 2 < NCHUNKS) issue(ch + 2, (ch + 2) % 3);

        const uint32_t aS = sA0 + (uint32_t)stg * STAGE_BYTES;
        const uint32_t bS = sB0 + (uint32_t)stg * STAGE_BYTES;
#pragma unroll
        for (int ks = 0; ks < 2; ks++) {
            uint32_t a[4][4];
#pragma unroll
            for (int ma = 0; ma < 4; ma++) {
                int row = wm * 64 + ma * 16 + (lane & 15);
                int ck  = 2 * ks + (lane >> 4);
                uint32_t ad = aS + (uint32_t)(row * PITCH + ck * 8) * 2u;
                asm volatile("ldmatrix.sync.aligned.m8n8.x4.shared.b16 {%0,%1,%2,%3}, [%4];"
                             : "=r"(a[ma][0]), "=r"(a[ma][1]), "=r"(a[ma][2]), "=r"(a[ma][3])
                             : "r"(ad));
            }
            uint32_t b[8][2];
#pragma unroll
            for (int p = 0; p < 4; p++) {
                int row = wn * 64 + p * 16 + (lane & 7) + ((lane >> 4) << 3);
                int ck  = 2 * ks + ((lane >> 3) & 1);
                uint32_t bd = bS + (uint32_t)(row * PITCH + ck * 8) * 2u;
                asm volatile("ldmatrix.sync.aligned.m8n8.x4.shared.b16 {%0,%1,%2,%3}, [%4];"
                             : "=r"(b[2 * p][0]), "=r"(b[2 * p][1]),
                               "=r"(b[2 * p + 1][0]), "=r"(b[2 * p + 1][1])
                             : "r"(bd));
            }
#pragma unroll
            for (int ma = 0; ma < 4; ma++)
#pragma unroll
                for (int na = 0; na < 8; na++) {
                    asm volatile(
                        "mma.sync.aligned.m16n8k16.row.col.f32.bf16.bf16.f32 "
                        "{%0,%1,%2,%3}, {%4,%5,%6,%7}, {%8,%9}, {%0,%1,%2,%3};"
                        : "+f"(c[ma][na][0]), "+f"(c[ma][na][1]),
                          "+f"(c[ma][na][2]), "+f"(c[ma][na][3])
                        : "r"(a[ma][0]), "r"(a[ma][1]), "r"(a[ma][2]), "r"(a[ma][3]),
                          "r"(b[na][0]), "r"(b[na][1]));
                }
        }
        __syncthreads();
    }

#pragma unroll
    for (int ma = 0; ma < 4; ma++) {
#pragma unroll
        for (int na = 0; na < 8; na++) {
            int col = wn * 64 + na * 8 + (lane & 3) * 2;
            float b0 = s_bias[col], b1 = s_bias[col + 1];
            int r0 = m0 + wm * 64 + ma * 16 + (lane >> 2);
            __nv_bfloat162 v0 = __floats2bfloat162_rn(c[ma][na][0] + b0, c[ma][na][1] + b1);
            __nv_bfloat162 v1 = __floats2bfloat162_rn(c[ma][na][2] + b0, c[ma][na][3] + b1);
            *(__nv_bfloat162*)(g_preh + (size_t)r0 * DICT + n0 + col)       = v0;
            *(__nv_bfloat162*)(g_preh + (size_t)(r0 + 8) * DICT + n0 + col) = v1;
        }
    }
}

// ---------------- K2: top-64 screen + Dot2 exact decision --------------------
__device__ __forceinline__ unsigned sortable16(unsigned h) {
    return (h & 0x8000u) ? ((~h) & 0xFFFFu) : (h | 0x8000u);
}
__device__ __forceinline__ float key_to_float(unsigned k) {
    unsigned b = (k & 0x8000u) ? (k ^ 0x8000u) : ((~k) & 0xFFFFu);
    return __uint_as_float(b << 16);
}
__device__ __forceinline__ void two_sum(float s, float h, float& t, float& e) {
    t = s + h;
    float z = t - s;
    e = (s - (t - z)) + (h - z);
}
// warp-aggregated histogram add. ALL 32 lanes must call this (convergent).
__device__ __forceinline__ void wagg_add(unsigned* hist, unsigned bin) {
    unsigned m = __match_any_sync(0xffffffffu, bin);
    if ((__ffs(m) - 1) == (int)(threadIdx.x & 31))
        atomicAdd(&hist[bin], (unsigned)__popc(m));
}

#define TOPK_T 512
#define KPT    24              // u32 regs per thread (48 keys)

__global__ __launch_bounds__(TOPK_T)
void topk_select(const float* __restrict__ x,
                 const float* __restrict__ wenc,
                 const float* __restrict__ benc) {
    __shared__ unsigned hist[256];
    __shared__ unsigned hist2[256];
    __shared__ int s_b1, s_need, s_ccnt;
    __shared__ int    s_cidx[CAND_CAP];
    __shared__ double s_cval[CAND_CAP];
    __shared__ float  s_x[D_MODEL];

    const int row  = blockIdx.x;
    const int tid  = threadIdx.x;
    const int wid  = tid >> 5;
    const int lane = tid & 31;

    // keys in registers: reg k holds dict idx {2*(tid+k*512), +1}
    unsigned key2[KPT];
    const unsigned* pre32 = (const unsigned*)(g_preh + (size_t)row * DICT);
#pragma unroll
    for (int k = 0; k < KPT; k++) {
        unsigned w = pre32[tid + k * TOPK_T];
        key2[k] = sortable16(w & 0xFFFFu) | (sortable16(w >> 16) << 16);
    }
    const float* xr = x + (size_t)row * D_MODEL;
    for (int i = tid; i < D_MODEL; i += TOPK_T) s_x[i] = xr[i];
    if (tid < 256) { hist[tid] = 0; hist2[tid] = 0; }
    __syncthreads();

    // pass 1: high byte, warp-aggregated (unconditional -> convergent, safe)
#pragma unroll
    for (int k = 0; k < KPT; k++) {
        unsigned v = key2[k];
        wagg_add(hist, (v >> 8) & 0xFFu);
        wagg_add(hist, v >> 24);
    }
    __syncthreads();
    if (tid == 0) {
        int cum = 0, b;
        for (b = 255; b >= 0; --b) {
            int cc = (int)hist[b];
            if (cum + cc >= K_TOP) break;
            cum += cc;
        }
        s_b1 = b; s_need = K_TOP - cum;
    }
    __syncthreads();
    const unsigned b1 = (unsigned)s_b1;
    int need = s_need;
    // pass 2: few matching keys -> plain predicated atomics (no collectives)
#pragma unroll
    for (int k = 0; k < KPT; k++) {
        unsigned v = key2[k];
        if (((v >> 8) & 0xFFu) == b1) atomicAdd(&hist2[v & 0xFFu], 1u);
        if ((v >> 24) == b1)          atomicAdd(&hist2[(v >> 16) & 0xFFu], 1u);
    }
    __syncthreads();
    if (tid == 0) {
        int cum = 0, b;
        for (b = 255; b >= 0; --b) {
            int cc = (int)hist2[b];
            if (cum + cc >= need) break;
            cum += cc;
        }
        s_b1 = (int)((b1 << 8) | (unsigned)b);
        s_ccnt = 0;
    }
    __syncthreads();
    const float candLo = key_to_float((unsigned)s_b1) - MARGIN;

    // collect candidates from registers
#pragma unroll
    for (int k = 0; k < KPT; k++) {
        unsigned v = key2[k];
        int j = tid + k * TOPK_T;
        float f0 = key_to_float(v & 0xFFFFu);
        float f1 = key_to_float(v >> 16);
        if (f0 >= candLo) {
            int p = atomicAdd(&s_ccnt, 1);
            if (p < CAND_CAP) s_cidx[p] = 2 * j;
        }
        if (f1 >= candLo) {
            int p = atomicAdd(&s_ccnt, 1);
            if (p < CAND_CAP) s_cidx[p] = 2 * j + 1;
        }
    }
    __syncthreads();
    const int ccnt = s_ccnt < CAND_CAP ? s_ccnt : CAND_CAP;

    // compensated fp32 dot (Dot2); decisions == fp64 path
    for (int cnd = wid; cnd < ccnt; cnd += TOPK_T / 32) {
        const int fidx = s_cidx[cnd];
        const float* wr = wenc + (size_t)fidx * D_MODEL;
        float s = 0.f, comp = 0.f;
#pragma unroll
        for (int t = 0; t < 24; t++) {
            int d = t * 32 + lane;
            float a = s_x[d], b = wr[d];
            float h = a * b;
            float r = fmaf(a, b, -h);
            float tnew, e;
            two_sum(s, h, tnew, e);
            s = tnew;
            comp += e + r;
        }
#pragma unroll
        for (int off = 16; off > 0; off >>= 1) {
            float s2 = __shfl_down_sync(0xffffffffu, s, off);
            float c2 = __shfl_down_sync(0xffffffffu, comp, off);
            float tnew, e;
            two_sum(s, s2, tnew, e);
            s = tnew;
            comp += c2 + e;
        }
        if (lane == 0)
            s_cval[cnd] = (double)s + (double)comp + (double)benc[fidx];
    }
    __syncthreads();

    // parallel exact rank (value desc, index asc)
    int* irow   = g_idx + (size_t)row * K_TOP;
    float* vrow = g_val + (size_t)row * K_TOP;
    for (int cnd = tid; cnd < ccnt; cnd += TOPK_T) {
        double v = s_cval[cnd];
        int ix = s_cidx[cnd];
        int rank = 0;
        for (int j = 0; j < ccnt; j++) {
            double vj = s_cval[j];
            rank += (vj > v) || (vj == v && s_cidx[j] < ix);
        }
        if (rank < K_TOP) {
            irow[rank] = ix;
            vrow[rank] = fmaxf((float)v, 0.f);
        }
    }
}

// ---------------- K2b: dense acts = zeros + scatter top-64 ----------------
__global__ __launch_bounds__(256)
void acts_fill(float* __restrict__ acts_out) {
    const int row = blockIdx.x;
    const int tid = threadIdx.x;
    float* arow = acts_out + (size_t)row * DICT;
    float4 z = make_float4(0.f, 0.f, 0.f, 0.f);
#pragma unroll
    for (int i = 0; i < DICT / 4 / 256; i++)
        ((float4*)arow)[tid + i * 256] = z;
    __syncthreads();
    if (tid < K_TOP)
        arow[g_idx[(size_t)row * K_TOP + tid]] = g_val[(size_t)row * K_TOP + tid];
}

// ---------------- K3: sparse decoder ----------------
__global__ void decode_kernel(float* __restrict__ recon) {
    __shared__ int   sidx[K_TOP];
    __shared__ float sval[K_TOP];
    const int row = blockIdx.x;
    const int tid = threadIdx.x;
    if (tid < K_TOP) {
        sidx[tid] = g_idx[(size_t)row * K_TOP + tid];
        sval[tid] = g_val[(size_t)row * K_TOP + tid];
    }
    __syncthreads();

    float a0 = 0.f, a1 = 0.f, a2 = 0.f;
#pragma unroll 8
    for (int j = 0; j < K_TOP; j++) {
        float v = sval[j];
        const float* wr = g_wdt + (size_t)sidx[j] * D_MODEL;
        a0 = fmaf(v, wr[tid],       a0);
        a1 = fmaf(v, wr[tid + 256], a1);
        a2 = fmaf(v, wr[tid + 512], a2);
    }
    float* o = recon + (size_t)row * D_MODEL;
    o[tid]       = a0;
    o[tid + 256] = a1;
    o[tid + 512] = a2;
}

// ---------------- launch ----------------
extern "C" void kernel_launch(void* const* d_in, const int* in_sizes, int n_in,
                              void* d_out, int out_size) {
    const float* x    = (const float*)d_in[0];
    const float* wenc = (const float*)d_in[1];
    const float* benc = (const float*)d_in[2];
    const float* wdec = (const float*)d_in[3];
    (void)in_sizes; (void)n_in; (void)out_size;

    float* out_recon = (float*)d_out;
    float* out_acts  = out_recon + (size_t)B_ROWS * D_MODEL;

    {
        __nv_bfloat16* xb; cudaGetSymbolAddress((void**)&xb, g_xb);
        __nv_bfloat16* wb; cudaGetSymbolAddress((void**)&wb, g_wb);
        int nx4 = B_ROWS * D_MODEL / 4;
        int nw4 = DICT * D_MODEL / 4;
        convert_bf16_kernel<<<(nx4 + 255) / 256, 256>>>(x, xb, nx4);
        convert_bf16_kernel<<<(nw4 + 255) / 256, 256>>>(wenc, wb, nw4);
    }
    {
        dim3 grid(DICT / 32, D_MODEL / 32);
        dim3 blk(32, 8);
        transpose_wdec_kernel<<<grid, blk>>>(wdec);
    }
    {
        cudaFuncSetAttribute(gemm_enc_mma, cudaFuncAttributeMaxDynamicSharedMemorySize,
                             GEMM_SMEM);
        dim3 grid(DICT / 128, B_ROWS / 128);
        gemm_enc_mma<<<grid, 128, GEMM_SMEM>>>(benc);
    }
    topk_select<<<B_ROWS, TOPK_T>>>(x, wenc, benc);
    decode_kernel<<<B_ROWS, 256>>>(out_recon);
    acts_fill<<<B_ROWS, 256>>>(out_acts);
}

// round 10
// speedup vs baseline: 1.3613x; 1.3613x over previous
#include <cuda_runtime.h>
#include <cuda_bf16.h>
#include <stdint.h>

#define B_ROWS   4096
#define D_MODEL  768
#define DICT     24576
#define K_TOP    64
#define CAND_CAP 512
#define MARGIN   0.1f

// ---------------- scratch (device globals) ----------------
__device__ __nv_bfloat16 g_xb[(size_t)B_ROWS * D_MODEL];    // x in bf16
__device__ __nv_bfloat16 g_wb[(size_t)DICT * D_MODEL];      // W_enc in bf16
__device__ __nv_bfloat16 g_preh[(size_t)B_ROWS * DICT];     // screened pre_acts (bf16)
__device__ float g_wdt[(size_t)DICT * D_MODEL];             // W_dec transposed
__device__ int   g_idx[(size_t)B_ROWS * K_TOP];
__device__ float g_val[(size_t)B_ROWS * K_TOP];

__device__ __forceinline__ uint32_t smem_u32(const void* p) {
    uint32_t a;
    asm("{ .reg .u64 t; cvta.to.shared.u64 t, %1; cvt.u32.u64 %0, t; }" : "=r"(a) : "l"(p));
    return a;
}

// ---------------- K0a: fp32 -> bf16 converts ----------------
__global__ void convert_bf16_kernel(const float* __restrict__ src,
                                    __nv_bfloat16* __restrict__ dst, int n4) {
    int i = blockIdx.x * blockDim.x + threadIdx.x;
    if (i < n4) {
        float4 v = ((const float4*)src)[i];
        __nv_bfloat162* o = (__nv_bfloat162*)dst;
        o[2 * i]     = __floats2bfloat162_rn(v.x, v.y);
        o[2 * i + 1] = __floats2bfloat162_rn(v.z, v.w);
    }
}

// ---------------- K0b: transpose W_dec [D][F] -> g_wdt [F][D] ----------------
__global__ void transpose_wdec_kernel(const float* __restrict__ wdec) {
    __shared__ float s[32][33];
    int f0 = blockIdx.x * 32;
    int d0 = blockIdx.y * 32;
    int tx = threadIdx.x, ty = threadIdx.y;
#pragma unroll
    for (int i = 0; i < 4; i++)
        s[ty + i * 8][tx] = wdec[(size_t)(d0 + ty + i * 8) * DICT + f0 + tx];
    __syncthreads();
#pragma unroll
    for (int i = 0; i < 4; i++)
        g_wdt[(size_t)(f0 + ty + i * 8) * D_MODEL + d0 + tx] = s[tx][ty + i * 8];
}

// ---------------- K1: bf16 mma.sync screening GEMM, 64x64 warp tiles ---------
#define PITCH 40
#define KCH   32
#define NCHUNKS (D_MODEL / KCH)   // 24
#define STAGE_BYTES (128 * PITCH * 2)
#define GEMM_SMEM   (6 * STAGE_BYTES)

__device__ __forceinline__ void cp16(uint32_t saddr, const void* g) {
    asm volatile("cp.async.ca.shared.global [%0], [%1], 16;" :: "r"(saddr), "l"(g));
}

__global__ __launch_bounds__(128, 2)
void gemm_enc_mma(const float* __restrict__ benc) {
    extern __shared__ __align__(128) char dsm[];
    __shared__ float s_bias[128];

    const int tid  = threadIdx.x;
    const int wid  = tid >> 5;
    const int lane = tid & 31;
    const int wm   = wid & 1;
    const int wn   = wid >> 1;
    const int m0 = blockIdx.y * 128;
    const int n0 = blockIdx.x * 128;

    if (tid < 128) s_bias[tid] = benc[n0 + tid];

    const __nv_bfloat16* Ag = g_xb + (size_t)m0 * D_MODEL;
    const __nv_bfloat16* Bg = g_wb + (size_t)n0 * D_MODEL;

    const uint32_t sA0 = smem_u32(dsm);
    const uint32_t sB0 = sA0 + 3 * STAGE_BYTES;

    auto issue = [&](int ch, int stg) {
#pragma unroll
        for (int i = 0; i < 4; i++) {
            int seg = tid + (i << 7);
            int r = seg >> 2, c = seg & 3;
            uint32_t so = (uint32_t)stg * STAGE_BYTES + (uint32_t)(r * PITCH + c * 8) * 2u;
            cp16(sA0 + so, Ag + (size_t)r * D_MODEL + ch * KCH + c * 8);
            cp16(sB0 + so, Bg + (size_t)r * D_MODEL + ch * KCH + c * 8);
        }
        asm volatile("cp.async.commit_group;" ::: "memory");
    };

    float c[4][8][4];
#pragma unroll
    for (int i = 0; i < 4; i++)
#pragma unroll
        for (int j = 0; j < 8; j++)
#pragma unroll
            for (int q = 0; q < 4; q++) c[i][j][q] = 0.f;

    issue(0, 0);
    issue(1, 1);

#pragma unroll 1
    for (int ch = 0; ch < NCHUNKS; ch++) {
        const int stg = ch % 3;
        if (ch + 1 < NCHUNKS)
            asm volatile("cp.async.wait_group 1;" ::: "memory");
        else
            asm volatile("cp.async.wait_group 0;" ::: "memory");
        __syncthreads();
        if (ch + 2 < NCHUNKS) issue(ch + 2, (ch + 2) % 3);

        const uint32_t aS = sA0 + (uint32_t)stg * STAGE_BYTES;
        const uint32_t bS = sB0 + (uint32_t)stg * STAGE_BYTES;
#pragma unroll
        for (int ks = 0; ks < 2; ks++) {
            uint32_t a[4][4];
#pragma unroll
            for (int ma = 0; ma < 4; ma++) {
                int row = wm * 64 + ma * 16 + (lane & 15);
                int ck  = 2 * ks + (lane >> 4);
                uint32_t ad = aS + (uint32_t)(row * PITCH + ck * 8) * 2u;
                asm volatile("ldmatrix.sync.aligned.m8n8.x4.shared.b16 {%0,%1,%2,%3}, [%4];"
                             : "=r"(a[ma][0]), "=r"(a[ma][1]), "=r"(a[ma][2]), "=r"(a[ma][3])
                             : "r"(ad));
            }
            uint32_t b[8][2];
#pragma unroll
            for (int p = 0; p < 4; p++) {
                int row = wn * 64 + p * 16 + (lane & 7) + ((lane >> 4) << 3);
                int ck  = 2 * ks + ((lane >> 3) & 1);
                uint32_t bd = bS + (uint32_t)(row * PITCH + ck * 8) * 2u;
                asm volatile("ldmatrix.sync.aligned.m8n8.x4.shared.b16 {%0,%1,%2,%3}, [%4];"
                             : "=r"(b[2 * p][0]), "=r"(b[2 * p][1]),
                               "=r"(b[2 * p + 1][0]), "=r"(b[2 * p + 1][1])
                             : "r"(bd));
            }
#pragma unroll
            for (int ma = 0; ma < 4; ma++)
#pragma unroll
                for (int na = 0; na < 8; na++) {
                    asm volatile(
                        "mma.sync.aligned.m16n8k16.row.col.f32.bf16.bf16.f32 "
                        "{%0,%1,%2,%3}, {%4,%5,%6,%7}, {%8,%9}, {%0,%1,%2,%3};"
                        : "+f"(c[ma][na][0]), "+f"(c[ma][na][1]),
                          "+f"(c[ma][na][2]), "+f"(c[ma][na][3])
                        : "r"(a[ma][0]), "r"(a[ma][1]), "r"(a[ma][2]), "r"(a[ma][3]),
                          "r"(b[na][0]), "r"(b[na][1]));
                }
        }
        __syncthreads();
    }

#pragma unroll
    for (int ma = 0; ma < 4; ma++) {
#pragma unroll
        for (int na = 0; na < 8; na++) {
            int col = wn * 64 + na * 8 + (lane & 3) * 2;
            float b0 = s_bias[col], b1 = s_bias[col + 1];
            int r0 = m0 + wm * 64 + ma * 16 + (lane >> 2);
            __nv_bfloat162 v0 = __floats2bfloat162_rn(c[ma][na][0] + b0, c[ma][na][1] + b1);
            __nv_bfloat162 v1 = __floats2bfloat162_rn(c[ma][na][2] + b0, c[ma][na][3] + b1);
            *(__nv_bfloat162*)(g_preh + (size_t)r0 * DICT + n0 + col)       = v0;
            *(__nv_bfloat162*)(g_preh + (size_t)(r0 + 8) * DICT + n0 + col) = v1;
        }
    }
}

// ---------------- K2: top-64 via bisection threshold + Dot2 exact decision ---
__device__ __forceinline__ void two_sum(float s, float h, float& t, float& e) {
    t = s + h;
    float z = t - s;
    e = (s - (t - z)) + (h - z);
}

#define TOPK_T 512
#define KPT    24              // u32 regs per thread (48 bf16 keys)

__global__ __launch_bounds__(TOPK_T)
void topk_select(const float* __restrict__ x,
                 const float* __restrict__ wenc,
                 const float* __restrict__ benc) {
    __shared__ int s_cnt;
    __shared__ int s_ccnt;
    __shared__ int    s_cidx[CAND_CAP];
    __shared__ double s_cval[CAND_CAP];
    __shared__ float  s_x[D_MODEL];

    const int row  = blockIdx.x;
    const int tid  = threadIdx.x;
    const int wid  = tid >> 5;
    const int lane = tid & 31;

    // raw bf16 pair keys in registers: reg k holds dict idx {2*(tid+k*512), +1}
    unsigned key2[KPT];
    const unsigned* pre32 = (const unsigned*)(g_preh + (size_t)row * DICT);
#pragma unroll
    for (int k = 0; k < KPT; k++) key2[k] = pre32[tid + k * TOPK_T];

    const float* xr = x + (size_t)row * D_MODEL;
    for (int i = tid; i < D_MODEL; i += TOPK_T) s_x[i] = xr[i];
    __syncthreads();

    // ---- bisection for threshold t_ok: largest t seen with count(>=t) >= 64
    float tl = 0.f, th = 16.f, t_ok = 0.f;
#pragma unroll 1
    for (int it = 0; it < 12; it++) {
        float t = 0.5f * (tl + th);
        __syncthreads();
        if (tid == 0) s_cnt = 0;
        __syncthreads();
        int myc = 0;
#pragma unroll
        for (int k = 0; k < KPT; k++) {
            unsigned v = key2[k];
            float f0 = __uint_as_float(v << 16);
            float f1 = __uint_as_float(v & 0xFFFF0000u);
            myc += (f0 >= t) + (f1 >= t);
        }
#pragma unroll
        for (int off = 16; off > 0; off >>= 1)
            myc += __shfl_down_sync(0xffffffffu, myc, off);
        if (lane == 0 && myc) atomicAdd(&s_cnt, myc);
        __syncthreads();
        int cnt = s_cnt;
        if (cnt >= K_TOP) {
            t_ok = t; tl = t;
            if (cnt <= 128) break;           // uniform decision (cnt from smem)
        } else {
            th = t;
        }
    }
    const float candLo = t_ok - MARGIN;

    __syncthreads();
    if (tid == 0) s_ccnt = 0;
    __syncthreads();

    // ---- collect candidates from registers
#pragma unroll
    for (int k = 0; k < KPT; k++) {
        unsigned v = key2[k];
        int j = tid + k * TOPK_T;
        float f0 = __uint_as_float(v << 16);
        float f1 = __uint_as_float(v & 0xFFFF0000u);
        if (f0 >= candLo) {
            int p = atomicAdd(&s_ccnt, 1);
            if (p < CAND_CAP) s_cidx[p] = 2 * j;
        }
        if (f1 >= candLo) {
            int p = atomicAdd(&s_ccnt, 1);
            if (p < CAND_CAP) s_cidx[p] = 2 * j + 1;
        }
    }
    __syncthreads();
    const int ccnt = s_ccnt < CAND_CAP ? s_ccnt : CAND_CAP;

    // ---- compensated fp32 dot (Dot2); decisions == fp64 path
    for (int cnd = wid; cnd < ccnt; cnd += TOPK_T / 32) {
        const int fidx = s_cidx[cnd];
        const float* wr = wenc + (size_t)fidx * D_MODEL;
        float s = 0.f, comp = 0.f;
#pragma unroll
        for (int t = 0; t < 24; t++) {
            int d = t * 32 + lane;
            float a = s_x[d], b = wr[d];
            float h = a * b;
            float r = fmaf(a, b, -h);
            float tnew, e;
            two_sum(s, h, tnew, e);
            s = tnew;
            comp += e + r;
        }
#pragma unroll
        for (int off = 16; off > 0; off >>= 1) {
            float s2 = __shfl_down_sync(0xffffffffu, s, off);
            float c2 = __shfl_down_sync(0xffffffffu, comp, off);
            float tnew, e;
            two_sum(s, s2, tnew, e);
            s = tnew;
            comp += c2 + e;
        }
        if (lane == 0)
            s_cval[cnd] = (double)s + (double)comp + (double)benc[fidx];
    }
    __syncthreads();

    // ---- parallel exact rank (value desc, index asc)
    int* irow   = g_idx + (size_t)row * K_TOP;
    float* vrow = g_val + (size_t)row * K_TOP;
    for (int cnd = tid; cnd < ccnt; cnd += TOPK_T) {
        double v = s_cval[cnd];
        int ix = s_cidx[cnd];
        int rank = 0;
        for (int j = 0; j < ccnt; j++) {
            double vj = s_cval[j];
            rank += (vj > v) || (vj == v && s_cidx[j] < ix);
        }
        if (rank < K_TOP) {
            irow[rank] = ix;
            vrow[rank] = fmaxf((float)v, 0.f);
        }
    }
}

// ---------------- K2b: dense acts = zeros + scatter top-64 ----------------
__global__ __launch_bounds__(256)
void acts_fill(float* __restrict__ acts_out) {
    const int row = blockIdx.x;
    const int tid = threadIdx.x;
    float* arow = acts_out + (size_t)row * DICT;
    float4 z = make_float4(0.f, 0.f, 0.f, 0.f);
#pragma unroll
    for (int i = 0; i < DICT / 4 / 256; i++)
        ((float4*)arow)[tid + i * 256] = z;
    __syncthreads();
    if (tid < K_TOP)
        arow[g_idx[(size_t)row * K_TOP + tid]] = g_val[(size_t)row * K_TOP + tid];
}

// ---------------- K3: sparse decoder ----------------
__global__ void decode_kernel(float* __restrict__ recon) {
    __shared__ int   sidx[K_TOP];
    __shared__ float sval[K_TOP];
    const int row = blockIdx.x;
    const int tid = threadIdx.x;
    if (tid < K_TOP) {
        sidx[tid] = g_idx[(size_t)row * K_TOP + tid];
        sval[tid] = g_val[(size_t)row * K_TOP + tid];
    }
    __syncthreads();

    float a0 = 0.f, a1 = 0.f, a2 = 0.f;
#pragma unroll 8
    for (int j = 0; j < K_TOP; j++) {
        float v = sval[j];
        const float* wr = g_wdt + (size_t)sidx[j] * D_MODEL;
        a0 = fmaf(v, wr[tid],       a0);
        a1 = fmaf(v, wr[tid + 256], a1);
        a2 = fmaf(v, wr[tid + 512], a2);
    }
    float* o = recon + (size_t)row * D_MODEL;
    o[tid]       = a0;
    o[tid + 256] = a1;
    o[tid + 512] = a2;
}

// ---------------- launch ----------------
extern "C" void kernel_launch(void* const* d_in, const int* in_sizes, int n_in,
                              void* d_out, int out_size) {
    const float* x    = (const float*)d_in[0];
    const float* wenc = (const float*)d_in[1];
    const float* benc = (const float*)d_in[2];
    const float* wdec = (const float*)d_in[3];
    (void)in_sizes; (void)n_in; (void)out_size;

    float* out_recon = (float*)d_out;
    float* out_acts  = out_recon + (size_t)B_ROWS * D_MODEL;

    {
        __nv_bfloat16* xb; cudaGetSymbolAddress((void**)&xb, g_xb);
        __nv_bfloat16* wb; cudaGetSymbolAddress((void**)&wb, g_wb);
        int nx4 = B_ROWS * D_MODEL / 4;
        int nw4 = DICT * D_MODEL / 4;
        convert_bf16_kernel<<<(nx4 + 255) / 256, 256>>>(x, xb, nx4);
        convert_bf16_kernel<<<(nw4 + 255) / 256, 256>>>(wenc, wb, nw4);
    }
    {
        dim3 grid(DICT / 32, D_MODEL / 32);
        dim3 blk(32, 8);
        transpose_wdec_kernel<<<grid, blk>>>(wdec);
    }
    {
        cudaFuncSetAttribute(gemm_enc_mma, cudaFuncAttributeMaxDynamicSharedMemorySize,
                             GEMM_SMEM);
        dim3 grid(DICT / 128, B_ROWS / 128);
        gemm_enc_mma<<<grid, 128, GEMM_SMEM>>>(benc);
    }
    topk_select<<<B_ROWS, TOPK_T>>>(x, wenc, benc);
    decode_kernel<<<B_ROWS, 256>>>(out_recon);
    acts_fill<<<B_ROWS, 256>>>(out_acts);
}